// round 6
// baseline (speedup 1.0000x reference)
#include <cuda_runtime.h>

// ctrl_pts: (16,64,64,4) f32 | uspan/vspan: (512,) i32 | Nu/Nv: (512,4) f32
// out: (16,512,512,3) f32
#define BATCH   16
#define MCTRL   64
#define NCTRL   64
#define OUTN    512
#define PDEG    3

__device__ __forceinline__ float rcp_approx(float x) {
    float r;
    asm("rcp.approx.f32 %0, %1;" : "=f"(r) : "f"(x));
    return r;
}

// ---------------------------------------------------------------------------
// Fused kernel. Block = (b, 4 u-rows), 128 threads, 8 blocks/SM.
// Phase 1: A[4][64] into smem (exact 4-window per u).
// Phase 2: thread g owns v-group 4g..4g+3; its 4x4 Nv weights are expanded
//          once into a shared 5-window (span shifts <=1 within the group)
//          and reused across the 4 u-rows. Scalar FMA throughout.
// ---------------------------------------------------------------------------
__global__ __launch_bounds__(128, 8)
void surf_fused(const float4* __restrict__ ctrl,
                const int*    __restrict__ uspan,
                const int4*   __restrict__ vspan4,
                const float4* __restrict__ Nu4,
                const float4* __restrict__ Nv4,
                float4*       __restrict__ out)
{
    __shared__ float4 sA[4 * NCTRL];          // 4 KB

    int t  = threadIdx.x;                     // 0..127
    int b  = blockIdx.y;
    int u0 = blockIdx.x * 4;

    // ---------------- Phase 1: build A tile (4 rows x 64 n) ----------------
    {
        int n  = t & (NCTRL - 1);
        int up = t >> 6;                      // 0..1 ; handles up and up+2
#pragma unroll
        for (int half = 0; half < 2; half++) {
            int ul = up + 2 * half;
            int u  = u0 + ul;
            int iu0 = __ldg(uspan + u) - PDEG;
            const float4* __restrict__ base =
                ctrl + ((b * MCTRL + iu0) * NCTRL + n);
            float4 c0 = __ldg(base + 0 * NCTRL);
            float4 c1 = __ldg(base + 1 * NCTRL);
            float4 c2 = __ldg(base + 2 * NCTRL);
            float4 c3 = __ldg(base + 3 * NCTRL);
            float4 nu = __ldg(Nu4 + u);

            float4 acc;
            acc.x = nu.x*c0.x + nu.y*c1.x + nu.z*c2.x + nu.w*c3.x;
            acc.y = nu.x*c0.y + nu.y*c1.y + nu.z*c2.y + nu.w*c3.y;
            acc.z = nu.x*c0.z + nu.y*c1.z + nu.z*c2.z + nu.w*c3.z;
            acc.w = nu.x*c0.w + nu.y*c1.w + nu.z*c2.w + nu.w*c3.w;

            sA[ul * NCTRL + n] = acc;
        }
    }
    __syncthreads();

    // ---------------- Phase 2: evaluate 4 rows x 512 v ----------------
    int g = t;                                // v-group: v = 4g..4g+3

    int4 vs  = __ldg(vspan4 + g);
    int  iv0 = vs.x - PDEG;

    // Expand 4x4 weights into a shared 5-window (scalar, 20 regs).
    float w[4][5];
    {
        int dk1 = vs.y - vs.x, dk2 = vs.z - vs.x, dk3 = vs.w - vs.x;
        int dks[4] = {0, dk1, dk2, dk3};
#pragma unroll
        for (int k = 0; k < 4; k++) {
            float4 nv = __ldg(Nv4 + 4 * g + k);
            bool sh = dks[k] != 0;
            w[k][0] = sh ? 0.0f : nv.x;
            w[k][1] = sh ? nv.x : nv.y;
            w[k][2] = sh ? nv.y : nv.z;
            w[k][3] = sh ? nv.z : nv.w;
            w[k][4] = sh ? nv.w : 0.0f;
        }
    }

#pragma unroll
    for (int i = 0; i < 4; i++) {
        int u = u0 + i;

        const float4* __restrict__ Ab = sA + i * NCTRL + iv0;
        float4 a0 = Ab[0];
        float4 a1 = Ab[1];
        float4 a2 = Ab[2];
        float4 a3 = Ab[3];
        float4 a4 = Ab[4];

        float res[12];
#pragma unroll
        for (int k = 0; k < 4; k++) {
            float sx = w[k][0]*a0.x + w[k][1]*a1.x + w[k][2]*a2.x
                     + w[k][3]*a3.x + w[k][4]*a4.x;
            float sy = w[k][0]*a0.y + w[k][1]*a1.y + w[k][2]*a2.y
                     + w[k][3]*a3.y + w[k][4]*a4.y;
            float sz = w[k][0]*a0.z + w[k][1]*a1.z + w[k][2]*a2.z
                     + w[k][3]*a3.z + w[k][4]*a4.z;
            float sw = w[k][0]*a0.w + w[k][1]*a1.w + w[k][2]*a2.w
                     + w[k][3]*a3.w + w[k][4]*a4.w;

            float inv = rcp_approx(sw);
            res[k * 3 + 0] = sx * inv;
            res[k * 3 + 1] = sy * inv;
            res[k * 3 + 2] = sz * inv;
        }

        float4* __restrict__ o =
            out + (size_t)(b * OUTN + u) * (OUTN * 3 / 4) + 3 * g;
        o[0] = make_float4(res[0], res[1],  res[2],  res[3]);
        o[1] = make_float4(res[4], res[5],  res[6],  res[7]);
        o[2] = make_float4(res[8], res[9],  res[10], res[11]);
    }
}

extern "C" void kernel_launch(void* const* d_in, const int* in_sizes, int n_in,
                              void* d_out, int out_size)
{
    const float4* ctrl   = (const float4*)d_in[0];
    const int*    uspan  = (const int*)   d_in[1];
    const int4*   vspan4 = (const int4*)  d_in[2];
    const float4* Nu4    = (const float4*)d_in[3];
    const float4* Nv4    = (const float4*)d_in[4];
    float4*       out    = (float4*)      d_out;

    dim3 grid(OUTN / 4, BATCH);               // 128 x 16 = 2048 blocks
    surf_fused<<<grid, 128>>>(ctrl, uspan, vspan4, Nu4, Nv4, out);
}

// round 7
// speedup vs baseline: 1.1807x; 1.1807x over previous
#include <cuda_runtime.h>

// ctrl_pts: (16,64,64,4) f32 | uspan/vspan: (512,) i32 | Nu/Nv: (512,4) f32
// out: (16,512,512,3) f32
#define BATCH   16
#define MCTRL   64
#define NCTRL   64
#define OUTN    512
#define PDEG    3

typedef unsigned long long ull;

// ---- packed f32x2 helpers ------------------------------------------------
__device__ __forceinline__ ull pack2(float a, float b) {
    ull r;
    asm("mov.b64 %0, {%1,%2};" : "=l"(r) : "f"(a), "f"(b));
    return r;
}
__device__ __forceinline__ void unpack2(ull v, float& a, float& b) {
    asm("mov.b64 {%0,%1}, %2;" : "=f"(a), "=f"(b) : "l"(v));
}
__device__ __forceinline__ ull mul2(ull a, ull b) {
    ull d;
    asm("mul.rn.f32x2 %0, %1, %2;" : "=l"(d) : "l"(a), "l"(b));
    return d;
}
__device__ __forceinline__ ull fma2(ull a, ull b, ull c) {
    ull d;
    asm("fma.rn.f32x2 %0, %1, %2, %3;" : "=l"(d) : "l"(a), "l"(b), "l"(c));
    return d;
}
__device__ __forceinline__ float rcp_approx(float x) {
    float r;
    asm("rcp.approx.f32 %0, %1;" : "=f"(r) : "f"(x));
    return r;
}

// ---------------------------------------------------------------------------
// Fused kernel. Block = (b, 4 u-rows), 256 threads, 4 blocks/SM (50% occ).
// Phase 1: A[4][64] into smem — exactly ONE entry per thread.
// Phase 2: thread g owns v-pair (2g, 2g+1); its 2x4 Nv weights expanded once
//          into a 5-window (span shifts <=1 within the pair), f32x2-packed
//          (20 regs), reused across 4 u-rows. 8 points per thread.
// ---------------------------------------------------------------------------
__global__ __launch_bounds__(256, 4)
void surf_fused(const float4* __restrict__ ctrl,
                const int*    __restrict__ uspan,
                const int2*   __restrict__ vspan2,
                const float4* __restrict__ Nu4,
                const float4* __restrict__ Nv4,
                float2*       __restrict__ out)
{
    __shared__ float4 sA[4 * NCTRL];          // 4 KB

    int t  = threadIdx.x;                     // 0..255
    int b  = blockIdx.y;
    int u0 = blockIdx.x * 4;

    // ---------------- Phase 1: one A entry per thread ----------------
    {
        int n  = t & (NCTRL - 1);
        int ul = t >> 6;                      // 0..3
        int u  = u0 + ul;
        int iu0 = __ldg(uspan + u) - PDEG;
        const float4* __restrict__ base =
            ctrl + ((b * MCTRL + iu0) * NCTRL + n);
        float4 c0 = __ldg(base + 0 * NCTRL);
        float4 c1 = __ldg(base + 1 * NCTRL);
        float4 c2 = __ldg(base + 2 * NCTRL);
        float4 c3 = __ldg(base + 3 * NCTRL);
        float4 nu = __ldg(Nu4 + u);

        float4 acc;
        acc.x = nu.x*c0.x + nu.y*c1.x + nu.z*c2.x + nu.w*c3.x;
        acc.y = nu.x*c0.y + nu.y*c1.y + nu.z*c2.y + nu.w*c3.y;
        acc.z = nu.x*c0.z + nu.y*c1.z + nu.z*c2.z + nu.w*c3.z;
        acc.w = nu.x*c0.w + nu.y*c1.w + nu.z*c2.w + nu.w*c3.w;

        sA[ul * NCTRL + n] = acc;
    }
    __syncthreads();

    // ---------------- Phase 2: v-pair (2g, 2g+1), 4 rows ----------------
    int g = t;
    int2 vs  = __ldg(vspan2 + g);
    int  iv0 = vs.x - PDEG;
    bool sh  = vs.y != vs.x;                  // second v shifted by one

    ull wp[2][5];
    {
        float4 nv0 = __ldg(Nv4 + 2 * g);
        float4 nv1 = __ldg(Nv4 + 2 * g + 1);
        wp[0][0] = pack2(nv0.x, nv0.x);
        wp[0][1] = pack2(nv0.y, nv0.y);
        wp[0][2] = pack2(nv0.z, nv0.z);
        wp[0][3] = pack2(nv0.w, nv0.w);
        wp[0][4] = pack2(0.0f, 0.0f);
        float w0 = sh ? 0.0f : nv1.x;
        float w1 = sh ? nv1.x : nv1.y;
        float w2 = sh ? nv1.y : nv1.z;
        float w3 = sh ? nv1.z : nv1.w;
        float w4 = sh ? nv1.w : 0.0f;
        wp[1][0] = pack2(w0, w0);
        wp[1][1] = pack2(w1, w1);
        wp[1][2] = pack2(w2, w2);
        wp[1][3] = pack2(w3, w3);
        wp[1][4] = pack2(w4, w4);
    }

#pragma unroll
    for (int i = 0; i < 4; i++) {
        int u = u0 + i;

        const ulonglong2* __restrict__ Ab =
            (const ulonglong2*)(sA + i * NCTRL + iv0);
        ulonglong2 a0 = Ab[0];
        ulonglong2 a1 = Ab[1];
        ulonglong2 a2 = Ab[2];
        ulonglong2 a3 = Ab[3];
        ulonglong2 a4 = Ab[4];

        float res[6];
#pragma unroll
        for (int k = 0; k < 2; k++) {
            ull axy = mul2(wp[k][0], a0.x);
            ull azw = mul2(wp[k][0], a0.y);
            axy = fma2(wp[k][1], a1.x, axy);
            azw = fma2(wp[k][1], a1.y, azw);
            axy = fma2(wp[k][2], a2.x, axy);
            azw = fma2(wp[k][2], a2.y, azw);
            axy = fma2(wp[k][3], a3.x, axy);
            azw = fma2(wp[k][3], a3.y, azw);
            axy = fma2(wp[k][4], a4.x, axy);
            azw = fma2(wp[k][4], a4.y, azw);

            float sx, sy, sz, sw;
            unpack2(axy, sx, sy);
            unpack2(azw, sz, sw);
            float inv = rcp_approx(sw);
            res[k * 3 + 0] = sx * inv;
            res[k * 3 + 1] = sy * inv;
            res[k * 3 + 2] = sz * inv;
        }

        // Row of 512 points x 12B = 768 float2. Thread g covers 24B at 3g.
        float2* __restrict__ o =
            out + (size_t)(b * OUTN + u) * (OUTN * 3 / 2) + 3 * g;
        o[0] = make_float2(res[0], res[1]);
        o[1] = make_float2(res[2], res[3]);
        o[2] = make_float2(res[4], res[5]);
    }
}

extern "C" void kernel_launch(void* const* d_in, const int* in_sizes, int n_in,
                              void* d_out, int out_size)
{
    const float4* ctrl   = (const float4*)d_in[0];
    const int*    uspan  = (const int*)   d_in[1];
    const int2*   vspan2 = (const int2*)  d_in[2];
    const float4* Nu4    = (const float4*)d_in[3];
    const float4* Nv4    = (const float4*)d_in[4];
    float2*       out    = (float2*)      d_out;

    dim3 grid(OUTN / 4, BATCH);               // 128 x 16 = 2048 blocks
    surf_fused<<<grid, 256>>>(ctrl, uspan, vspan2, Nu4, Nv4, out);
}